// round 15
// baseline (speedup 1.0000x reference)
#include <cuda_runtime.h>
#include <math.h>
#include <stdint.h>

#define S 2048
#define B 32
#define D 1024
#define NCHUNK 16
#define CHUNK (S / NCHUNK)   // 128
#define RPW (CHUNK / 8)      // 16 rows per warp
#define STAGES 3
#define KT 64
#define KS0 16               // semi GEMM:   k=1024 -> 16 x 64
#define KS3 32               // output GEMM: k=2048 -> 32 x 64

#define K1_SMEM (8 * STAGES * 256 * 16)   // 96 KB dynamic

// Static scratch (no allocations allowed). NEVER passed as host-side kernel
// args — always referenced from device code (R4/R5 bug).
__device__ float g_semi[B * D];                    // 128 KB
__device__ float g_p0[(size_t)KS0 * B * D];        // 2 MB
__device__ float g_pm[B * NCHUNK];
__device__ float g_pl[B * NCHUNK];
__device__ float g_pacc[(size_t)B * NCHUNK * D];   // 2 MB
__device__ float g_xcat[B * 2 * D];                // 256 KB
__device__ float g_p3[(size_t)KS3 * B * D];        // 4 MB
__device__ int   g_cnt0[16];                       // last-block tickets (zero-init,
__device__ int   g_cnt1[B];                        //  reset by last block each call)
__device__ int   g_cnt3[16];

// ---------------------------------------------------------------------------
// Partial-GEMM body: one 64-k slice, float4 global loads, one sync pair.
//   P[ks][r][j0..j0+63] = sum_{k in [ks*64,(ks+1)*64)} A[r][k] * W[j][k]
// 256 threads, 2x4 outputs per thread.
// ---------------------------------------------------------------------------
__device__ __forceinline__ void gemm_body(
    const float* __restrict__ A, const float* __restrict__ W,
    float* __restrict__ P, int astride, int wstride)
{
    int jt = blockIdx.x;
    int ks = blockIdx.y;
    int j0 = jt * 64;
    int k0 = ks * KT;

    __shared__ float Xs[32][KT + 1];
    __shared__ float Ws[64][KT + 1];

    int t = threadIdx.x;

    // Xs: 32 rows x 16 float4 = 512 float4, 2 per thread
    #pragma unroll
    for (int i = t; i < 32 * 16; i += 256) {
        int r = i >> 4, q = i & 15;
        float4 v = *(const float4*)(A + (size_t)r * astride + k0 + 4 * q);
        Xs[r][4*q+0] = v.x; Xs[r][4*q+1] = v.y;
        Xs[r][4*q+2] = v.z; Xs[r][4*q+3] = v.w;
    }
    // Ws: 64 rows x 16 float4 = 1024 float4, 4 per thread
    #pragma unroll
    for (int i = t; i < 64 * 16; i += 256) {
        int r = i >> 4, q = i & 15;
        float4 v = *(const float4*)(W + (size_t)(j0 + r) * wstride + k0 + 4 * q);
        Ws[r][4*q+0] = v.x; Ws[r][4*q+1] = v.y;
        Ws[r][4*q+2] = v.z; Ws[r][4*q+3] = v.w;
    }
    __syncthreads();

    int tb = t & 15;
    int tj = t >> 4;
    float acc[2][4] = {{0.f,0.f,0.f,0.f},{0.f,0.f,0.f,0.f}};
    #pragma unroll 8
    for (int k = 0; k < KT; k++) {
        float x0 = Xs[2 * tb][k];
        float x1 = Xs[2 * tb + 1][k];
        float w0 = Ws[4 * tj + 0][k];
        float w1 = Ws[4 * tj + 1][k];
        float w2 = Ws[4 * tj + 2][k];
        float w3 = Ws[4 * tj + 3][k];
        acc[0][0] += x0 * w0; acc[0][1] += x0 * w1;
        acc[0][2] += x0 * w2; acc[0][3] += x0 * w3;
        acc[1][0] += x1 * w0; acc[1][1] += x1 * w1;
        acc[1][2] += x1 * w2; acc[1][3] += x1 * w3;
    }

    #pragma unroll
    for (int i = 0; i < 2; i++)
        #pragma unroll
        for (int q = 0; q < 4; q++)
            P[((size_t)ks * B + (2 * tb + i)) * D + j0 + 4 * tj + q] = acc[i][q];
}

// ---------------------------------------------------------------------------
// G0: semi GEMM partials + fused sum (last block per j-tile) -> g_semi
// grid = (16, KS0), 256 threads
// ---------------------------------------------------------------------------
__global__ void __launch_bounds__(256) g0_semi(
    const float* __restrict__ h, const float* __restrict__ Wi)
{
    gemm_body(h, Wi, g_p0, D, D);

    int jt = blockIdx.x, t = threadIdx.x;
    __threadfence();
    __syncthreads();
    __shared__ int s_last;
    if (t == 0) s_last = (atomicAdd(&g_cnt0[jt], 1) == KS0 - 1) ? 1 : 0;
    __syncthreads();
    if (!s_last) return;
    if (t == 0) g_cnt0[jt] = 0;                  // reset for next graph replay

    int j0 = jt * 64;
    #pragma unroll
    for (int oi = 0; oi < 8; oi++) {             // 2048 outputs / 256 threads
        int idx = t + oi * 256;
        int bb = idx >> 6, jj = idx & 63;
        float s = 0.f;
        #pragma unroll
        for (int ks = 0; ks < KS0; ks++)
            s += g_p0[((size_t)ks * B + bb) * D + j0 + jj];
        g_semi[(size_t)bb * D + j0 + jj] = s;
    }
}

// ---------------------------------------------------------------------------
// K1: fused logits + online softmax + weighted accumulation (one HBM pass),
// per-batch combine fused via last-block. grid = (NCHUNK, B), 256 thr,
// warp-per-row, 3-deep cp.async pipeline. (unchanged from R13 — 74% DRAM)
// ---------------------------------------------------------------------------
__global__ void __launch_bounds__(256, 2) k1_online(
    const float* __restrict__ input, const float* __restrict__ h)
{
    extern __shared__ float4 stg[];              // 8 * STAGES * 256 float4
    int c = blockIdx.x, b = blockIdx.y;
    int t = threadIdx.x, warp = t >> 5, lane = t & 31;

    float4 sem[8];
    const float4* semi4 = (const float4*)(g_semi + b * D);
    #pragma unroll
    for (int j = 0; j < 8; j++) sem[j] = semi4[lane + 32 * j];

    float4* wst = stg + warp * (STAGES * 256);
    int s0 = c * CHUNK + warp * RPW;
    const float4* base = (const float4*)(input + ((size_t)s0 * B + b) * D);
    const size_t rstride = (size_t)B * D / 4;

    #pragma unroll
    for (int k = 0; k < STAGES; k++) {
        const float4* src = base + (size_t)k * rstride;
        float4* dst = wst + k * 256;
        #pragma unroll
        for (int j = 0; j < 8; j++) {
            uint32_t sa = (uint32_t)__cvta_generic_to_shared(dst + lane + 32 * j);
            asm volatile("cp.async.cg.shared.global [%0], [%1], 16;"
                         :: "r"(sa), "l"(src + lane + 32 * j));
        }
        asm volatile("cp.async.commit_group;");
    }

    float4 acc[8];
    #pragma unroll
    for (int j = 0; j < 8; j++) acc[j] = make_float4(0.f, 0.f, 0.f, 0.f);
    float m = -INFINITY, l = 0.f;

    for (int i = 0; i < RPW; i++) {
        asm volatile("cp.async.wait_group %0;" :: "n"(STAGES - 1));
        float4* cur = wst + (i % STAGES) * 256;
        float4 x[8];
        #pragma unroll
        for (int j = 0; j < 8; j++) x[j] = cur[lane + 32 * j];

        if (i + STAGES < RPW) {
            const float4* src = base + (size_t)(i + STAGES) * rstride;
            #pragma unroll
            for (int j = 0; j < 8; j++) {
                uint32_t sa = (uint32_t)__cvta_generic_to_shared(cur + lane + 32 * j);
                asm volatile("cp.async.cg.shared.global [%0], [%1], 16;"
                             :: "r"(sa), "l"(src + lane + 32 * j));
            }
        }
        asm volatile("cp.async.commit_group;");

        float p0 = 0.f, p1 = 0.f;
        #pragma unroll
        for (int j = 0; j < 8; j++) {
            p0 += x[j].x * sem[j].x + x[j].y * sem[j].y;
            p1 += x[j].z * sem[j].z + x[j].w * sem[j].w;
        }
        float p = p0 + p1;
        #pragma unroll
        for (int o = 16; o; o >>= 1) p += __shfl_xor_sync(0xffffffffu, p, o);
        if (p > m) {
            float sc = __expf(m - p);            // exp(-inf)=0 first row
            #pragma unroll
            for (int j = 0; j < 8; j++) {
                acc[j].x *= sc; acc[j].y *= sc; acc[j].z *= sc; acc[j].w *= sc;
            }
            l *= sc; m = p;
        }
        float w = __expf(p - m);
        l += w;
        #pragma unroll
        for (int j = 0; j < 8; j++) {
            acc[j].x += w * x[j].x; acc[j].y += w * x[j].y;
            acc[j].z += w * x[j].z; acc[j].w += w * x[j].w;
        }
    }

    // merge 8 warps; reuse stage smem
    __shared__ float sm[8], sl[8];
    if (lane == 0) { sm[warp] = m; sl[warp] = l; }
    asm volatile("cp.async.wait_group 0;");
    __syncthreads();

    float M = -INFINITY;
    #pragma unroll
    for (int w = 0; w < 8; w++) M = fmaxf(M, sm[w]);
    float L = 0.f;
    #pragma unroll
    for (int w = 0; w < 8; w++) L += sl[w] * __expf(sm[w] - M);
    float f = __expf(m - M);

    float4* sacc = stg;
    #pragma unroll
    for (int j = 0; j < 8; j++) {
        float4 a = acc[j];
        a.x *= f; a.y *= f; a.z *= f; a.w *= f;
        sacc[warp * 256 + lane + 32 * j] = a;
    }
    __syncthreads();
    float4 s = make_float4(0.f, 0.f, 0.f, 0.f);
    #pragma unroll
    for (int w = 0; w < 8; w++) {
        float4 a = sacc[w * 256 + t];
        s.x += a.x; s.y += a.y; s.z += a.z; s.w += a.w;
    }
    ((float4*)(g_pacc + (size_t)(b * NCHUNK + c) * D))[t] = s;
    if (t == 0) { g_pm[b * NCHUNK + c] = M; g_pl[b * NCHUNK + c] = L; }

    // ---- fused combine: last block per b ----
    __threadfence();
    __syncthreads();
    __shared__ int s_last;
    if (t == 0) s_last = (atomicAdd(&g_cnt1[b], 1) == NCHUNK - 1) ? 1 : 0;
    __syncthreads();
    if (!s_last) return;
    if (t == 0) g_cnt1[b] = 0;                   // reset for next graph replay

    __shared__ float spm[NCHUNK], spl[NCHUNK];
    if (t < NCHUNK) { spm[t] = g_pm[b * NCHUNK + t]; spl[t] = g_pl[b * NCHUNK + t]; }
    __syncthreads();

    float MM = -INFINITY;
    #pragma unroll
    for (int cc = 0; cc < NCHUNK; cc++) MM = fmaxf(MM, spm[cc]);
    float LL = 0.f;
    #pragma unroll
    for (int cc = 0; cc < NCHUNK; cc++) LL += spl[cc] * __expf(spm[cc] - MM);
    float invL = 1.f / LL;

    const float4* pb = (const float4*)g_pacc + (size_t)b * NCHUNK * 256;
    float4 st = make_float4(0.f, 0.f, 0.f, 0.f);
    #pragma unroll
    for (int cc = 0; cc < NCHUNK; cc++) {
        float4 v = pb[(size_t)cc * 256 + t];
        float e = __expf(spm[cc] - MM);
        st.x += v.x * e; st.y += v.y * e; st.z += v.z * e; st.w += v.w * e;
    }
    st.x *= invL; st.y *= invL; st.z *= invL; st.w *= invL;

    float4* xc = (float4*)g_xcat + (size_t)b * 512;
    xc[t] = st;
    xc[256 + t] = ((const float4*)h)[b * 256 + t];
}

// ---------------------------------------------------------------------------
// G3: output GEMM partials + fused reduce+tanh (last block per j-tile).
// grid = (16, KS3) = 512 blocks, 256 threads.
// ---------------------------------------------------------------------------
__global__ void __launch_bounds__(256) g3_out(
    const float* __restrict__ Wo, float* __restrict__ out)
{
    gemm_body(g_xcat, Wo, g_p3, 2 * D, 2 * D);

    int jt = blockIdx.x, t = threadIdx.x;
    __threadfence();
    __syncthreads();
    __shared__ int s_last;
    if (t == 0) s_last = (atomicAdd(&g_cnt3[jt], 1) == KS3 - 1) ? 1 : 0;
    __syncthreads();
    if (!s_last) return;
    if (t == 0) g_cnt3[jt] = 0;                  // reset for next graph replay

    int j0 = jt * 64;
    #pragma unroll
    for (int oi = 0; oi < 8; oi++) {             // 2048 outputs / 256 threads
        int idx = t + oi * 256;
        int bb = idx >> 6, jj = idx & 63;
        float s = 0.f;
        #pragma unroll
        for (int ks = 0; ks < KS3; ks++)
            s += g_p3[((size_t)ks * B + bb) * D + j0 + jj];
        out[(size_t)bb * D + j0 + jj] = tanhf(s);
    }
}

// ---------------------------------------------------------------------------
extern "C" void kernel_launch(void* const* d_in, const int* in_sizes, int n_in,
                              void* d_out, int out_size) {
    const float* input = (const float*)d_in[0];   // [S, B, D]
    const float* h     = (const float*)d_in[1];   // [B, D]
    const float* Wi    = (const float*)d_in[2];   // [D, D]
    const float* Wo    = (const float*)d_in[3];   // [D, 2D]
    float* out         = (float*)d_out;           // [B, D]

    cudaFuncSetAttribute(k1_online, cudaFuncAttributeMaxDynamicSharedMemorySize,
                         K1_SMEM);

    g0_semi<<<dim3(16, KS0), 256>>>(h, Wi);                 // semi + fused sum
    k1_online<<<dim3(NCHUNK, B), 256, K1_SMEM>>>(input, h); // fused pass + combine
    g3_out<<<dim3(16, KS3), 256>>>(Wo, out);                // GEMM + fused tanh
}

// round 17
// speedup vs baseline: 1.0766x; 1.0766x over previous
#include <cuda_runtime.h>
#include <math.h>
#include <stdint.h>

#define S 2048
#define B 32
#define D 1024
#define NCHUNK 16
#define CHUNK (S / NCHUNK)   // 128
#define RPW (CHUNK / 8)      // 16 rows per warp
#define STAGES 3
#define KT 64
#define KS0 16               // semi GEMM:   k=1024 -> 16 x 64
#define KS3 32               // output GEMM: k=2048 -> 32 x 64

#define K1_SMEM (8 * STAGES * 256 * 16)   // 96 KB dynamic

// Static scratch (no allocations allowed). NEVER passed as host-side kernel
// args — always referenced from device code (R4/R5 bug).
__device__ float g_semi[B * D];                    // 128 KB
__device__ float g_p0[(size_t)KS0 * B * D];        // 2 MB
__device__ float g_pm[B * NCHUNK];
__device__ float g_pl[B * NCHUNK];
__device__ float g_pacc[(size_t)B * NCHUNK * D];   // 2 MB
__device__ float g_xcat[B * 2 * D];                // 256 KB
__device__ float g_p3[(size_t)KS3 * B * D];        // 4 MB
__device__ int   g_cnt0[32];                       // last-block tickets (zero-init,
__device__ int   g_cnt1[B];                        //  reset by last block each call)
__device__ int   g_cnt3[32];

// ---------------------------------------------------------------------------
// Partial-GEMM body, 32x32 j-tile (high block-concurrency variant):
//   P[ks][r][j0..j0+31] = sum_{k in [ks*64,(ks+1)*64)} A[r][k] * W[j][k]
// 256 threads, 2x2 outputs per thread, one load->sync->compute phase.
// ---------------------------------------------------------------------------
__device__ __forceinline__ void gemm32(
    const float* __restrict__ A, const float* __restrict__ W,
    float* __restrict__ P, int astride, int wstride)
{
    int jt = blockIdx.x;         // 32 tiles of 32 j
    int ks = blockIdx.y;
    int j0 = jt * 32;
    int k0 = ks * KT;

    __shared__ float Xs[32][KT + 1];
    __shared__ float Ws[32][KT + 1];

    int t = threadIdx.x;

    // Xs: 32 rows x 16 float4 = 512 float4, 2 per thread
    #pragma unroll
    for (int i = t; i < 512; i += 256) {
        int r = i >> 4, q = i & 15;
        float4 v = *(const float4*)(A + (size_t)r * astride + k0 + 4 * q);
        Xs[r][4*q+0] = v.x; Xs[r][4*q+1] = v.y;
        Xs[r][4*q+2] = v.z; Xs[r][4*q+3] = v.w;
    }
    // Ws: 32 rows x 16 float4 = 512 float4, 2 per thread
    #pragma unroll
    for (int i = t; i < 512; i += 256) {
        int r = i >> 4, q = i & 15;
        float4 v = *(const float4*)(W + (size_t)(j0 + r) * wstride + k0 + 4 * q);
        Ws[r][4*q+0] = v.x; Ws[r][4*q+1] = v.y;
        Ws[r][4*q+2] = v.z; Ws[r][4*q+3] = v.w;
    }
    __syncthreads();

    int tb = t & 15;             // 16 groups x 2 b-rows
    int tj = t >> 4;             // 16 groups x 2 j-cols
    float a00 = 0.f, a01 = 0.f, a10 = 0.f, a11 = 0.f;
    #pragma unroll 16
    for (int k = 0; k < KT; k++) {
        float x0 = Xs[2 * tb][k];
        float x1 = Xs[2 * tb + 1][k];
        float w0 = Ws[2 * tj][k];
        float w1 = Ws[2 * tj + 1][k];
        a00 += x0 * w0; a01 += x0 * w1;
        a10 += x1 * w0; a11 += x1 * w1;
    }

    P[((size_t)ks * B + 2 * tb    ) * D + j0 + 2 * tj    ] = a00;
    P[((size_t)ks * B + 2 * tb    ) * D + j0 + 2 * tj + 1] = a01;
    P[((size_t)ks * B + 2 * tb + 1) * D + j0 + 2 * tj    ] = a10;
    P[((size_t)ks * B + 2 * tb + 1) * D + j0 + 2 * tj + 1] = a11;
}

// ---------------------------------------------------------------------------
// G0: semi GEMM partials + fused sum (last block per j-tile) -> g_semi
// grid = (32, KS0) = 512 blocks, 256 threads
// ---------------------------------------------------------------------------
__global__ void __launch_bounds__(256) g0_semi(
    const float* __restrict__ h, const float* __restrict__ Wi)
{
    gemm32(h, Wi, g_p0, D, D);

    int jt = blockIdx.x, t = threadIdx.x;
    __threadfence();
    __syncthreads();
    __shared__ int s_last;
    if (t == 0) s_last = (atomicAdd(&g_cnt0[jt], 1) == KS0 - 1) ? 1 : 0;
    __syncthreads();
    if (!s_last) return;
    if (t == 0) g_cnt0[jt] = 0;                  // reset for next graph replay

    int j0 = jt * 32;
    #pragma unroll
    for (int oi = 0; oi < 4; oi++) {             // 1024 outputs / 256 threads
        int idx = t + oi * 256;
        int bb = idx >> 5, jj = idx & 31;
        float s = 0.f;
        #pragma unroll
        for (int ks = 0; ks < KS0; ks++)
            s += g_p0[((size_t)ks * B + bb) * D + j0 + jj];
        g_semi[(size_t)bb * D + j0 + jj] = s;
    }
}

// ---------------------------------------------------------------------------
// K1: fused logits + online softmax + weighted accumulation (one HBM pass),
// per-batch combine fused via last-block. grid = (NCHUNK, B), 256 thr,
// warp-per-row, 3-deep cp.async pipeline. UNCHANGED (74% DRAM).
// ---------------------------------------------------------------------------
__global__ void __launch_bounds__(256, 2) k1_online(
    const float* __restrict__ input, const float* __restrict__ h)
{
    extern __shared__ float4 stg[];              // 8 * STAGES * 256 float4
    int c = blockIdx.x, b = blockIdx.y;
    int t = threadIdx.x, warp = t >> 5, lane = t & 31;

    float4 sem[8];
    const float4* semi4 = (const float4*)(g_semi + b * D);
    #pragma unroll
    for (int j = 0; j < 8; j++) sem[j] = semi4[lane + 32 * j];

    float4* wst = stg + warp * (STAGES * 256);
    int s0 = c * CHUNK + warp * RPW;
    const float4* base = (const float4*)(input + ((size_t)s0 * B + b) * D);
    const size_t rstride = (size_t)B * D / 4;

    #pragma unroll
    for (int k = 0; k < STAGES; k++) {
        const float4* src = base + (size_t)k * rstride;
        float4* dst = wst + k * 256;
        #pragma unroll
        for (int j = 0; j < 8; j++) {
            uint32_t sa = (uint32_t)__cvta_generic_to_shared(dst + lane + 32 * j);
            asm volatile("cp.async.cg.shared.global [%0], [%1], 16;"
                         :: "r"(sa), "l"(src + lane + 32 * j));
        }
        asm volatile("cp.async.commit_group;");
    }

    float4 acc[8];
    #pragma unroll
    for (int j = 0; j < 8; j++) acc[j] = make_float4(0.f, 0.f, 0.f, 0.f);
    float m = -INFINITY, l = 0.f;

    for (int i = 0; i < RPW; i++) {
        asm volatile("cp.async.wait_group %0;" :: "n"(STAGES - 1));
        float4* cur = wst + (i % STAGES) * 256;
        float4 x[8];
        #pragma unroll
        for (int j = 0; j < 8; j++) x[j] = cur[lane + 32 * j];

        if (i + STAGES < RPW) {
            const float4* src = base + (size_t)(i + STAGES) * rstride;
            #pragma unroll
            for (int j = 0; j < 8; j++) {
                uint32_t sa = (uint32_t)__cvta_generic_to_shared(cur + lane + 32 * j);
                asm volatile("cp.async.cg.shared.global [%0], [%1], 16;"
                             :: "r"(sa), "l"(src + lane + 32 * j));
            }
        }
        asm volatile("cp.async.commit_group;");

        float p0 = 0.f, p1 = 0.f;
        #pragma unroll
        for (int j = 0; j < 8; j++) {
            p0 += x[j].x * sem[j].x + x[j].y * sem[j].y;
            p1 += x[j].z * sem[j].z + x[j].w * sem[j].w;
        }
        float p = p0 + p1;
        #pragma unroll
        for (int o = 16; o; o >>= 1) p += __shfl_xor_sync(0xffffffffu, p, o);
        if (p > m) {
            float sc = __expf(m - p);            // exp(-inf)=0 first row
            #pragma unroll
            for (int j = 0; j < 8; j++) {
                acc[j].x *= sc; acc[j].y *= sc; acc[j].z *= sc; acc[j].w *= sc;
            }
            l *= sc; m = p;
        }
        float w = __expf(p - m);
        l += w;
        #pragma unroll
        for (int j = 0; j < 8; j++) {
            acc[j].x += w * x[j].x; acc[j].y += w * x[j].y;
            acc[j].z += w * x[j].z; acc[j].w += w * x[j].w;
        }
    }

    // merge 8 warps; reuse stage smem
    __shared__ float sm[8], sl[8];
    if (lane == 0) { sm[warp] = m; sl[warp] = l; }
    asm volatile("cp.async.wait_group 0;");
    __syncthreads();

    float M = -INFINITY;
    #pragma unroll
    for (int w = 0; w < 8; w++) M = fmaxf(M, sm[w]);
    float L = 0.f;
    #pragma unroll
    for (int w = 0; w < 8; w++) L += sl[w] * __expf(sm[w] - M);
    float f = __expf(m - M);

    float4* sacc = stg;
    #pragma unroll
    for (int j = 0; j < 8; j++) {
        float4 a = acc[j];
        a.x *= f; a.y *= f; a.z *= f; a.w *= f;
        sacc[warp * 256 + lane + 32 * j] = a;
    }
    __syncthreads();
    float4 s = make_float4(0.f, 0.f, 0.f, 0.f);
    #pragma unroll
    for (int w = 0; w < 8; w++) {
        float4 a = sacc[w * 256 + t];
        s.x += a.x; s.y += a.y; s.z += a.z; s.w += a.w;
    }
    ((float4*)(g_pacc + (size_t)(b * NCHUNK + c) * D))[t] = s;
    if (t == 0) { g_pm[b * NCHUNK + c] = M; g_pl[b * NCHUNK + c] = L; }

    // ---- fused combine: last block per b ----
    __threadfence();
    __syncthreads();
    __shared__ int s_last;
    if (t == 0) s_last = (atomicAdd(&g_cnt1[b], 1) == NCHUNK - 1) ? 1 : 0;
    __syncthreads();
    if (!s_last) return;
    if (t == 0) g_cnt1[b] = 0;                   // reset for next graph replay

    __shared__ float spm[NCHUNK], spl[NCHUNK];
    if (t < NCHUNK) { spm[t] = g_pm[b * NCHUNK + t]; spl[t] = g_pl[b * NCHUNK + t]; }
    __syncthreads();

    float MM = -INFINITY;
    #pragma unroll
    for (int cc = 0; cc < NCHUNK; cc++) MM = fmaxf(MM, spm[cc]);
    float LL = 0.f;
    #pragma unroll
    for (int cc = 0; cc < NCHUNK; cc++) LL += spl[cc] * __expf(spm[cc] - MM);
    float invL = 1.f / LL;

    const float4* pb = (const float4*)g_pacc + (size_t)b * NCHUNK * 256;
    float4 st = make_float4(0.f, 0.f, 0.f, 0.f);
    #pragma unroll
    for (int cc = 0; cc < NCHUNK; cc++) {
        float4 v = pb[(size_t)cc * 256 + t];
        float e = __expf(spm[cc] - MM);
        st.x += v.x * e; st.y += v.y * e; st.z += v.z * e; st.w += v.w * e;
    }
    st.x *= invL; st.y *= invL; st.z *= invL; st.w *= invL;

    float4* xc = (float4*)g_xcat + (size_t)b * 512;
    xc[t] = st;
    xc[256 + t] = ((const float4*)h)[b * 256 + t];
}

// ---------------------------------------------------------------------------
// G3: output GEMM partials + fused reduce+tanh (last block per j-tile).
// grid = (32, KS3) = 1024 blocks, 256 threads.
// ---------------------------------------------------------------------------
__global__ void __launch_bounds__(256) g3_out(
    const float* __restrict__ Wo, float* __restrict__ out)
{
    gemm32(g_xcat, Wo, g_p3, 2 * D, 2 * D);

    int jt = blockIdx.x, t = threadIdx.x;
    __threadfence();
    __syncthreads();
    __shared__ int s_last;
    if (t == 0) s_last = (atomicAdd(&g_cnt3[jt], 1) == KS3 - 1) ? 1 : 0;
    __syncthreads();
    if (!s_last) return;
    if (t == 0) g_cnt3[jt] = 0;                  // reset for next graph replay

    int j0 = jt * 32;
    #pragma unroll
    for (int oi = 0; oi < 4; oi++) {             // 1024 outputs / 256 threads
        int idx = t + oi * 256;
        int bb = idx >> 5, jj = idx & 31;
        float s = 0.f;
        #pragma unroll
        for (int ks = 0; ks < KS3; ks++)
            s += g_p3[((size_t)ks * B + bb) * D + j0 + jj];
        out[(size_t)bb * D + j0 + jj] = tanhf(s);
    }
}

// ---------------------------------------------------------------------------
extern "C" void kernel_launch(void* const* d_in, const int* in_sizes, int n_in,
                              void* d_out, int out_size) {
    const float* input = (const float*)d_in[0];   // [S, B, D]
    const float* h     = (const float*)d_in[1];   // [B, D]
    const float* Wi    = (const float*)d_in[2];   // [D, D]
    const float* Wo    = (const float*)d_in[3];   // [D, 2D]
    float* out         = (float*)d_out;           // [B, D]

    cudaFuncSetAttribute(k1_online, cudaFuncAttributeMaxDynamicSharedMemorySize,
                         K1_SMEM);

    g0_semi<<<dim3(32, KS0), 256>>>(h, Wi);                 // semi + fused sum
    k1_online<<<dim3(NCHUNK, B), 256, K1_SMEM>>>(input, h); // fused pass + combine
    g3_out<<<dim3(32, KS3), 256>>>(Wo, out);                // GEMM + fused tanh
}